// round 1
// baseline (speedup 1.0000x reference)
#include <cuda_runtime.h>

// ---------------------------------------------------------------------------
// VQ nearest-code quantization + cosine score.
// Inputs : d_in[0]=z [64,256,32,32] f32, d_in[1]=gt same, d_in[2]=codebook [1024,256] f32
// Output : concat( zq[B,H,W,C], cosine[B,W,C], idx_gt[B,H,W], idx[B,H,W] ) as f32
// ---------------------------------------------------------------------------

namespace {
constexpr int kC   = 256;
constexpr int kNE  = 1024;
constexpr int kHW  = 1024;           // 32*32
constexpr int kCHW = 256 * 1024;     // C*H*W
constexpr int kNTok = 64 * 1024;     // B*H*W = 65536 tokens per tensor
constexpr int kZQ  = kNTok * kC;     // 16777216
constexpr int kCOS = 64 * 32 * 256;  // 524288
constexpr int kOffCos  = kZQ;
constexpr int kOffIdxG = kZQ + kCOS;
constexpr int kOffIdxZ = kOffIdxG + kNTok;
}

// scratch (no allocations allowed)
__device__ float g_codeNorm[kNE];
__device__ float g_tokNorm[2 * kNTok];  // z tokens then gt tokens
__device__ int   g_idx[2 * kNTok];      // z indices then gt indices

// ---------------------------------------------------------------------------
__global__ void code_norm_kernel(const float* __restrict__ cb) {
    int j = blockIdx.x * blockDim.x + threadIdx.x;
    if (j >= kNE) return;
    const float* r = cb + j * kC;
    float s = 0.f;
    for (int c = 0; c < kC; ++c) s = fmaf(r[c], r[c], s);
    g_codeNorm[j] = s;
}

__global__ void tok_norm_kernel(const float* __restrict__ z,
                                const float* __restrict__ gt) {
    int t = blockIdx.x * blockDim.x + threadIdx.x;  // 0..131071
    if (t >= 2 * kNTok) return;
    const float* src = (t < kNTok) ? z : gt;
    int tl = t & (kNTok - 1);
    const float* p = src + (tl >> 10) * kCHW + (tl & 1023);
    float s = 0.f;
    for (int c = 0; c < kC; ++c) { float a = p[c * kHW]; s = fmaf(a, a, s); }
    g_tokNorm[t] = s;
}

// ---------------------------------------------------------------------------
// Argmin over 1024 codes. Block = 64 tokens; loops code chunks of 128.
// 256 threads as 16(tx: token dim) x 16(ty: code dim); micro-tile 4x8.
#define TM 64
#define CN 128
#define KC 32
#define CSTR 260  // KC*8 + 4 pad

__global__ __launch_bounds__(256, 2)
void argmin_kernel(const float* __restrict__ z, const float* __restrict__ gt,
                   const float* __restrict__ cb) {
    __shared__ float sTok[KC][TM + 4];
    __shared__ float sCode[16 * CSTR];
    __shared__ float sRv[16][TM];
    __shared__ int   sRi[16][TM];

    const int tid = threadIdx.x;
    const int tx = tid & 15, ty = tid >> 4;
    const int tile = blockIdx.x;                       // 0..2047
    const float* src = (tile < 1024) ? z : gt;
    const int tLocal = (tile & 1023) * TM;             // token base within tensor
    const float* gsrc = src + (tLocal >> 10) * kCHW + (tLocal & 1023);
    const int gTokBase = tile * TM;                    // into g_tokNorm / g_idx

    float s[4];
#pragma unroll
    for (int u = 0; u < 4; ++u) s[u] = g_tokNorm[gTokBase + tx * 4 + u];

    float best[4];
    int   bidx[4];
#pragma unroll
    for (int u = 0; u < 4; ++u) { best[u] = 3.4e38f; bidx[u] = 0; }

    for (int cc0 = 0; cc0 < kNE; cc0 += CN) {
        float acc[4][8];
#pragma unroll
        for (int i = 0; i < 4; ++i)
#pragma unroll
            for (int j = 0; j < 8; ++j) acc[i][j] = 0.f;

        for (int k0 = 0; k0 < kC; k0 += KC) {
            // token tile: [kk][tt], coalesced (tt fast)
#pragma unroll
            for (int i = tid; i < KC * TM; i += 256) {
                int kk = i >> 6, tt = i & 63;
                sTok[kk][tt] = gsrc[(k0 + kk) * kHW + tt];
            }
            // code tile: per-ty contiguous groups of 8 codes x KC
#pragma unroll
            for (int i = tid; i < CN * KC; i += 256) {
                int kk = i & 31, cc = i >> 5;
                sCode[(cc >> 3) * CSTR + kk * 8 + (cc & 7)] =
                    cb[(cc0 + cc) * kC + k0 + kk];
            }
            __syncthreads();
#pragma unroll
            for (int kk = 0; kk < KC; ++kk) {
                float4 a4 = *(const float4*)&sTok[kk][tx * 4];
                const float a[4] = {a4.x, a4.y, a4.z, a4.w};
                const float* bp = &sCode[ty * CSTR + kk * 8];
                float4 b0 = *(const float4*)bp;
                float4 b1 = *(const float4*)(bp + 4);
                const float bb[8] = {b0.x, b0.y, b0.z, b0.w,
                                     b1.x, b1.y, b1.z, b1.w};
#pragma unroll
                for (int i = 0; i < 4; ++i)
#pragma unroll
                    for (int j = 0; j < 8; ++j)
                        acc[i][j] = fmaf(a[i], bb[j], acc[i][j]);
            }
            __syncthreads();
        }
        // fold into running argmin, mimicking reference rounding:
        // d = (||x||^2 + ||e||^2) - 2*(x.e), non-fused final combination
#pragma unroll
        for (int j = 0; j < 8; ++j) {
            int code = cc0 + ty * 8 + j;
            float n = g_codeNorm[code];
#pragma unroll
            for (int i = 0; i < 4; ++i) {
                float d = __fadd_rn(__fadd_rn(s[i], n),
                                    -__fmul_rn(2.0f, acc[i][j]));
                if (d < best[i]) { best[i] = d; bidx[i] = code; }
            }
        }
    }

    // cross-ty reduction with first-index tie-break
#pragma unroll
    for (int i = 0; i < 4; ++i) {
        sRv[ty][tx * 4 + i] = best[i];
        sRi[ty][tx * 4 + i] = bidx[i];
    }
    __syncthreads();
    if (ty == 0) {
#pragma unroll
        for (int i = 0; i < 4; ++i) {
            int col = tx * 4 + i;
            float v = sRv[0][col];
            int   ix = sRi[0][col];
            for (int r = 1; r < 16; ++r) {
                float v2 = sRv[r][col];
                int   i2 = sRi[r][col];
                if (v2 < v || (v2 == v && i2 < ix)) { v = v2; ix = i2; }
            }
            g_idx[gTokBase + col] = ix;
        }
    }
}

// ---------------------------------------------------------------------------
__global__ void write_zq_kernel(const float* __restrict__ cb,
                                float* __restrict__ out) {
    int i = blockIdx.x * blockDim.x + threadIdx.x;  // over 4194304 float4s
    int t = i >> 6;
    int cq = i & 63;
    int idx = g_idx[t];  // z indices
    ((float4*)out)[i] = ((const float4*)(cb + idx * kC))[cq];
}

__global__ void write_idx_kernel(float* __restrict__ out) {
    int t = blockIdx.x * blockDim.x + threadIdx.x;
    if (t >= kNTok) return;
    out[kOffIdxG + t] = (float)g_idx[kNTok + t];  // idx_gt
    out[kOffIdxZ + t] = (float)g_idx[t];          // idx (z)
}

__global__ void cosine_kernel(const float* __restrict__ cb,
                              float* __restrict__ out) {
    int bw = blockIdx.x;          // b*32 + w
    int b = bw >> 5, w = bw & 31;
    int c = threadIdx.x;
    __shared__ int sig[32], siz[32];
    if (threadIdx.x < 32) {
        int h = threadIdx.x;
        int t = b * 1024 + h * 32 + w;
        sig[h] = g_idx[kNTok + t];  // gt
        siz[h] = g_idx[t];          // z
    }
    __syncthreads();
    float num = 0.f, ng = 0.f, nz = 0.f;
    for (int h = 0; h < 32; ++h) {
        float g = cb[sig[h] * kC + c];
        float q = cb[siz[h] * kC + c];
        num = fmaf(g, q, num);
        ng  = fmaf(g, g, ng);
        nz  = fmaf(q, q, nz);
    }
    float den = fmaxf(sqrtf(ng), 1e-8f) * fmaxf(sqrtf(nz), 1e-8f);
    out[kOffCos + bw * kC + c] = num / den;
}

// ---------------------------------------------------------------------------
extern "C" void kernel_launch(void* const* d_in, const int* in_sizes, int n_in,
                              void* d_out, int out_size) {
    const float* z  = (const float*)d_in[0];
    const float* gt = (const float*)d_in[1];
    const float* cb = (const float*)d_in[2];
    float* out = (float*)d_out;
    (void)in_sizes; (void)n_in; (void)out_size;

    code_norm_kernel<<<4, 256>>>(cb);
    tok_norm_kernel<<<(2 * kNTok + 255) / 256, 256>>>(z, gt);
    argmin_kernel<<<2048, 256>>>(z, gt, cb);
    write_zq_kernel<<<(kZQ / 4) / 256, 256>>>(cb, out);
    write_idx_kernel<<<(kNTok + 255) / 256, 256>>>(out);
    cosine_kernel<<<64 * 32, 256>>>(cb, out);
}